// round 3
// baseline (speedup 1.0000x reference)
#include <cuda_runtime.h>
#include <cfloat>
#include <cstddef>

#define NLAB 4096
#define LLAB 32
#define EDIM 300
#define KFLT 4
#define FEAT 512
#define BB 16
#define LL 512
#define SLAB (LLAB*EDIM)          /* 9600  */
#define KDIM (KFLT*EDIM)          /* 1200  */

typedef unsigned long long u64;

// ---------------- scratch (static device globals; no allocation) ----------------
__device__ float g_WrT[KDIM*FEAT];            // repacked conv weights [j][f], j = k*300+e
__device__ float g_lr0[NLAB*FEAT];            // conv+relu+maxpool output
__device__ float g_lr [NLAB*FEAT];            // after linear
__device__ float g_linwT[FEAT*FEAT];          // lin_w transposed [c][f]
__device__ float g_XT[BB*FEAT*LL];            // x transposed per batch [b][f][l]
__device__ float g_S [BB*NLAB*LL];            // logits / probs (134 MB)

// ---------------- f32x2 helpers (B300 packed fp32 FMA) ----------------
__device__ __forceinline__ u64 pack2(float x, float y) {
    u64 r; asm("mov.b64 %0, {%1, %2};" : "=l"(r) : "f"(x), "f"(y)); return r;
}
__device__ __forceinline__ void unpack2(u64 v, float& x, float& y) {
    asm("mov.b64 {%0, %1}, %2;" : "=f"(x), "=f"(y) : "l"(v));
}
__device__ __forceinline__ void ffma2(u64& d, u64 a, u64 b) {
    asm("fma.rn.f32x2 %0, %1, %2, %0;" : "+l"(d) : "l"(a), "l"(b));
}

// 8 k-steps of the 128x128 tile micro-kernel: 8 rows x 4 col-pairs per thread.
__device__ __forceinline__ void mm_step8(const float (*As)[132], const float (*Bs)[128],
                                         u64 acc[8][4], int ty, int tx) {
#pragma unroll
    for (int k = 0; k < 8; ++k) {
        u64 b2[4];
#pragma unroll
        for (int j = 0; j < 4; ++j)
            b2[j] = *(const u64*)&Bs[k][(tx + 16*j) * 2];
        float4 alo = *(const float4*)&As[k][ty*8];
        float4 ahi = *(const float4*)&As[k][ty*8 + 4];
        float av[8] = {alo.x, alo.y, alo.z, alo.w, ahi.x, ahi.y, ahi.z, ahi.w};
#pragma unroll
        for (int i = 0; i < 8; ++i) {
            u64 a2 = pack2(av[i], av[i]);
            ffma2(acc[i][0], a2, b2[0]);
            ffma2(acc[i][1], a2, b2[1]);
            ffma2(acc[i][2], a2, b2[2]);
            ffma2(acc[i][3], a2, b2[3]);
        }
    }
}

// ---------------- small prep kernels ----------------
__global__ void repack_w_kernel(const float* __restrict__ cw) {
    int idx = blockIdx.x * 256 + threadIdx.x;      // 614400 exact
    int f = idx & 511, j = idx >> 9;
    int k = j / EDIM, e = j % EDIM;
    g_WrT[idx] = cw[f * KDIM + e * KFLT + k];
}
__global__ void tr_linw_kernel(const float* __restrict__ lw) {
    int idx = blockIdx.x * 256 + threadIdx.x;      // 262144 exact
    int f = idx & 511, c = idx >> 9;
    g_linwT[idx] = lw[f * 512 + c];
}
__global__ void tr_x_kernel(const float* __restrict__ x) {
    int idx = blockIdx.x * 256 + threadIdx.x;      // 4194304 exact
    int l = idx & 511, f = (idx >> 9) & 511, b = idx >> 18;
    g_XT[idx] = x[(b << 18) + (l << 9) + f];
}

// ---------------- conv GEMM + bias + relu + maxpool(t) ----------------
// Block tile: M=128 rows (4 labels x 32 positions), 128 filter cols, K=1200.
__global__ __launch_bounds__(256, 2)
void conv_gemm_kernel(const float* __restrict__ lab, const float* __restrict__ convb) {
    __shared__ __align__(16) float As[8][132];
    __shared__ __align__(16) float Bs[8][128];
    __shared__ float Red[16][128];

    const int tid = threadIdx.x;
    const int ty = tid >> 4, tx = tid & 15;
    const int f0 = blockIdx.x * 128;
    const int n0 = blockIdx.y * 4;

    const int arow = tid >> 1, aseg = tid & 1;
    const int bk = tid >> 5, bc4 = (tid & 31) * 4;

    const long long TOTA = (long long)NLAB * SLAB;
    const long long abase = (long long)(n0 + (arow >> 5)) * SLAB + (arow & 31) * EDIM + aseg * 4;
    const size_t bbase = (size_t)bk * FEAT + f0 + bc4;

    u64 acc[8][4];
#pragma unroll
    for (int i = 0; i < 8; ++i) { acc[i][0]=0ull; acc[i][1]=0ull; acc[i][2]=0ull; acc[i][3]=0ull; }

    const int KT = KDIM / 8;   // 150
    float4 aR, bR;
    {
        long long ad = abase; if (ad > TOTA - 4) ad = TOTA - 4;
        aR = *(const float4*)(lab + ad);
        bR = *(const float4*)(g_WrT + bbase);
    }
#pragma unroll 1
    for (int kt = 0; kt < KT; ++kt) {
        __syncthreads();
        As[aseg*4+0][arow] = aR.x; As[aseg*4+1][arow] = aR.y;
        As[aseg*4+2][arow] = aR.z; As[aseg*4+3][arow] = aR.w;
        *(float4*)&Bs[bk][bc4] = bR;
        __syncthreads();
        if (kt + 1 < KT) {
            long long ad = abase + (long long)(kt + 1) * 8;
            if (ad > TOTA - 4) ad = TOTA - 4;
            aR = *(const float4*)(lab + ad);
            bR = *(const float4*)(g_WrT + bbase + (size_t)(kt + 1) * 8 * FEAT);
        }
        mm_step8(As, Bs, acc, ty, tx);
    }

    // epilogue: max over valid t (t = (ty&3)*8 + i, valid t < 29)
    const int ivmax = ((ty & 3) == 3) ? 5 : 8;
    float mm[8];
#pragma unroll
    for (int s = 0; s < 8; ++s) mm[s] = -FLT_MAX;
#pragma unroll
    for (int i = 0; i < 8; ++i) {
#pragma unroll
        for (int j = 0; j < 4; ++j) {
            float v0, v1; unpack2(acc[i][j], v0, v1);
            if (i < ivmax) {
                mm[2*j]   = fmaxf(mm[2*j],   v0);
                mm[2*j+1] = fmaxf(mm[2*j+1], v1);
            }
        }
    }
#pragma unroll
    for (int j = 0; j < 4; ++j) {
        Red[ty][(tx + 16*j)*2]     = mm[2*j];
        Red[ty][(tx + 16*j)*2 + 1] = mm[2*j+1];
    }
    __syncthreads();
#pragma unroll
    for (int q = 0; q < 2; ++q) {
        int o = tid + q * 256;
        int nl = o >> 7, f = o & 127;
        float v = fmaxf(fmaxf(Red[nl*4+0][f], Red[nl*4+1][f]),
                        fmaxf(Red[nl*4+2][f], Red[nl*4+3][f]));
        int fg = f0 + f;
        g_lr0[(size_t)(n0 + nl) * FEAT + fg] = fmaxf(v + convb[fg], 0.f);
    }
}

// ---------------- generic 128x128x512 fp32 GEMM (k-contiguous A, k-major B) ----------------
__global__ __launch_bounds__(256, 2)
void gemm512_kernel(const float* __restrict__ A, const float* __restrict__ B,
                    float* __restrict__ C, const float* __restrict__ bias,
                    size_t zA, size_t zB, size_t zC) {
    __shared__ __align__(16) float As[8][132];
    __shared__ __align__(16) float Bs[8][128];
    A += (size_t)blockIdx.z * zA;
    B += (size_t)blockIdx.z * zB;
    C += (size_t)blockIdx.z * zC;

    const int tid = threadIdx.x;
    const int ty = tid >> 4, tx = tid & 15;
    const int c0 = blockIdx.x * 128;
    const int m0 = blockIdx.y * 128;
    const int arow = tid >> 1, aseg = tid & 1;
    const int bk = tid >> 5, bc4 = (tid & 31) * 4;

    u64 acc[8][4];
#pragma unroll
    for (int i = 0; i < 8; ++i) { acc[i][0]=0ull; acc[i][1]=0ull; acc[i][2]=0ull; acc[i][3]=0ull; }

    const float* aPtr = A + (size_t)(m0 + arow) * 512 + aseg * 4;
    const float* bPtr = B + (size_t)bk * 512 + c0 + bc4;
    float4 aR = *(const float4*)aPtr;
    float4 bR = *(const float4*)bPtr;
#pragma unroll 1
    for (int kt = 0; kt < 64; ++kt) {
        __syncthreads();
        As[aseg*4+0][arow] = aR.x; As[aseg*4+1][arow] = aR.y;
        As[aseg*4+2][arow] = aR.z; As[aseg*4+3][arow] = aR.w;
        *(float4*)&Bs[bk][bc4] = bR;
        __syncthreads();
        if (kt + 1 < 64) {
            aR = *(const float4*)(aPtr + (kt + 1) * 8);
            bR = *(const float4*)(bPtr + (size_t)(kt + 1) * 8 * 512);
        }
        mm_step8(As, Bs, acc, ty, tx);
    }
#pragma unroll
    for (int i = 0; i < 8; ++i) {
        size_t rowOff = (size_t)(m0 + ty * 8 + i) * 512;
#pragma unroll
        for (int j = 0; j < 4; ++j) {
            float v0, v1; unpack2(acc[i][j], v0, v1);
            int cc = c0 + (tx + 16*j) * 2;
            if (bias) { v0 += bias[cc]; v1 += bias[cc + 1]; }
            C[rowOff + cc]     = v0;
            C[rowOff + cc + 1] = v1;
        }
    }
}

// ---------------- row softmax over L=512 ----------------
__global__ void softmax_kernel(float* __restrict__ S) {
    const size_t row = blockIdx.x;
    float* p = S + row * 512;
    const int tid = threadIdx.x;                 // 128 threads
    float v0 = p[tid], v1 = p[tid + 128], v2 = p[tid + 256], v3 = p[tid + 384];
    float mx = fmaxf(fmaxf(v0, v1), fmaxf(v2, v3));
#pragma unroll
    for (int o = 16; o > 0; o >>= 1) mx = fmaxf(mx, __shfl_xor_sync(0xffffffffu, mx, o));
    __shared__ float sm[4], ss[4];
    if ((tid & 31) == 0) sm[tid >> 5] = mx;
    __syncthreads();
    mx = fmaxf(fmaxf(sm[0], sm[1]), fmaxf(sm[2], sm[3]));
    v0 = expf(v0 - mx); v1 = expf(v1 - mx); v2 = expf(v2 - mx); v3 = expf(v3 - mx);
    float s = v0 + v1 + v2 + v3;
#pragma unroll
    for (int o = 16; o > 0; o >>= 1) s += __shfl_xor_sync(0xffffffffu, s, o);
    if ((tid & 31) == 0) ss[tid >> 5] = s;
    __syncthreads();
    s = ss[0] + ss[1] + ss[2] + ss[3];
    float inv = 1.0f / s;
    p[tid] = v0 * inv; p[tid + 128] = v1 * inv; p[tid + 256] = v2 * inv; p[tid + 384] = v3 * inv;
}

// ---------------- launch ----------------
extern "C" void kernel_launch(void* const* d_in, const int* in_sizes, int n_in,
                              void* d_out, int out_size) {
    const float *x = nullptr, *lab = nullptr, *cw = nullptr,
                *cb = nullptr, *lw = nullptr, *lb = nullptr;
    for (int i = 0; i < n_in; ++i) {
        switch (in_sizes[i]) {
            case 4194304:  x   = (const float*)d_in[i]; break;   // x (16,512,512)
            case 39321600: lab = (const float*)d_in[i]; break;   // label_reps (4096,32,300)
            case 614400:   cw  = (const float*)d_in[i]; break;   // conv_w (512,300,4)
            case 262144:   lw  = (const float*)d_in[i]; break;   // lin_w (512,512)
            case 512:      if (!cb) cb = (const float*)d_in[i];  // conv_b then lin_b
                           else     lb = (const float*)d_in[i];
                           break;
            default: break;                                      // label_length: unused
        }
    }

    float *plr0, *plr, *plinwT, *pXT, *pS;
    cudaGetSymbolAddress((void**)&plr0,   g_lr0);
    cudaGetSymbolAddress((void**)&plr,    g_lr);
    cudaGetSymbolAddress((void**)&plinwT, g_linwT);
    cudaGetSymbolAddress((void**)&pXT,    g_XT);
    cudaGetSymbolAddress((void**)&pS,     g_S);

    repack_w_kernel<<<2400, 256>>>(cw);
    tr_linw_kernel<<<1024, 256>>>(lw);
    tr_x_kernel<<<16384, 256>>>(x);

    // conv + relu + maxpool -> lr0 (4096 x 512)
    conv_gemm_kernel<<<dim3(4, 1024, 1), 256>>>(lab, cb);

    // linear: lr = lr0 @ lin_w^T + lin_b
    gemm512_kernel<<<dim3(4, 32, 1), 256>>>(plr0, plinwT, plr, lb, 0, 0, 0);

    // logits: S[b,n,l] = sum_f lr[n,f] * x[b,l,f]
    gemm512_kernel<<<dim3(4, 32, 16), 256>>>(plr, pXT, pS, nullptr,
                                             0, (size_t)FEAT * LL, (size_t)NLAB * LL);

    // softmax over l
    softmax_kernel<<<65536, 128>>>(pS);

    // out: O[b,n,f] = sum_l P[b,n,l] * x[b,l,f]
    gemm512_kernel<<<dim3(4, 32, 16), 256>>>(pS, x, (float*)d_out, nullptr,
                                             (size_t)NLAB * LL, (size_t)LL * FEAT,
                                             (size_t)NLAB * FEAT);
}

// round 7
// speedup vs baseline: 1.4349x; 1.4349x over previous
#include <cuda_runtime.h>
#include <cuda_bf16.h>
#include <cstdint>
#include <cfloat>
#include <cstddef>

#define NLAB 4096
#define FEAT 512
#define BB   16
#define LL   512
#define SLAB 9600            /* 32*300 per label */
#define KCONV 1216           /* 1200 padded to 19*64 */

typedef unsigned int u32;
typedef unsigned long long u64;

// ---------------- device scratch (static; no allocation) ----------------
__device__ __nv_bfloat16 g_lab_hi[NLAB*SLAB + 2048];
__device__ __nv_bfloat16 g_lab_lo[NLAB*SLAB + 2048];
__device__ __nv_bfloat16 g_wr_hi [FEAT*KCONV];
__device__ __nv_bfloat16 g_wr_lo [FEAT*KCONV];
__device__ __nv_bfloat16 g_x_hi  [BB*LL*FEAT];
__device__ __nv_bfloat16 g_x_lo  [BB*LL*FEAT];
__device__ __nv_bfloat16 g_xt_hi [BB*FEAT*LL];
__device__ __nv_bfloat16 g_xt_lo [BB*FEAT*LL];
__device__ __nv_bfloat16 g_lw_hi [FEAT*FEAT];
__device__ __nv_bfloat16 g_lw_lo [FEAT*FEAT];
__device__ __nv_bfloat16 g_lr0_hi[NLAB*FEAT];
__device__ __nv_bfloat16 g_lr0_lo[NLAB*FEAT];
__device__ __nv_bfloat16 g_lr_hi [NLAB*FEAT];
__device__ __nv_bfloat16 g_lr_lo [NLAB*FEAT];
__device__ float         g_S     [(size_t)BB*NLAB*LL];
__device__ __nv_bfloat16 g_P_hi  [(size_t)BB*NLAB*LL];
__device__ __nv_bfloat16 g_P_lo  [(size_t)BB*NLAB*LL];

// ---------------- helpers ----------------
__device__ __forceinline__ u32 smem_u32(const void* p) {
    u32 a;
    asm("{ .reg .u64 t; cvta.to.shared.u64 t, %1; cvt.u32.u64 %0, t; }" : "=r"(a) : "l"(p));
    return a;
}
__device__ __forceinline__ void cp16(u32 dst, const void* src) {
    asm volatile("cp.async.cg.shared.global [%0], [%1], 16;" :: "r"(dst), "l"(src));
}
__device__ __forceinline__ void cp8(u32 dst, const void* src) {
    asm volatile("cp.async.ca.shared.global [%0], [%1], 8;" :: "r"(dst), "l"(src));
}
#define CP_COMMIT() asm volatile("cp.async.commit_group;" ::: "memory")
#define CP_WAIT(n)  asm volatile("cp.async.wait_group %0;" :: "n"(n) : "memory")

#define LDSM4(r, a)                                                                     \
    asm volatile("ldmatrix.sync.aligned.m8n8.x4.shared.b16 {%0,%1,%2,%3}, [%4];"        \
        : "=r"((r)[0]), "=r"((r)[1]), "=r"((r)[2]), "=r"((r)[3]) : "r"(a))

__device__ __forceinline__ void mma16816(float* d, const u32* a, const u32* b) {
    asm volatile(
        "mma.sync.aligned.m16n8k16.row.col.f32.bf16.bf16.f32 "
        "{%0,%1,%2,%3},{%4,%5,%6,%7},{%8,%9},{%0,%1,%2,%3};"
        : "+f"(d[0]), "+f"(d[1]), "+f"(d[2]), "+f"(d[3])
        : "r"(a[0]), "r"(a[1]), "r"(a[2]), "r"(a[3]), "r"(b[0]), "r"(b[1]));
}
__device__ __forceinline__ void split2(float v, __nv_bfloat16& h, __nv_bfloat16& l) {
    h = __float2bfloat16(v);
    l = __float2bfloat16(v - __bfloat162float(h));
}

// smem geometry: 4 tiles (Ahi, Alo, Bhi, Blo) of 128 rows x 64 bf16, rows padded to 144B
#define TROW   144
#define TILE_B (128 * TROW)          /* 18432 */
#define STAGE  (4 * TILE_B)          /* 73728 */
#define SMEM_TOTAL (2 * STAGE)       /* 147456 */

// ================= split-bf16 HMMA GEMM (mma.sync m16n8k16) =================
// C[m,c] = sum_k A[m,k]*B[c,k], 3-product split for ~fp32 accuracy.
// MODE 0: conv  C[f,(n,t)]  A=wr, B=lab windows; epi: maxpool(t<29)+bias+relu -> lr0 hi/lo
// MODE 1: linear C[n,f]     A=lr0, B=lin_w;      epi: +bias -> lr hi/lo
// MODE 2: logits C[n,l]     A=lr, B=x[b];        epi: fp32 -> S
// MODE 3: out    C[n,f]     A=P[b], B=xt[b];     epi: fp32 -> d_out
template<int MODE>
__global__ void __launch_bounds__(256, 1) tgemm(
    const __nv_bfloat16* __restrict__ Ahi, const __nv_bfloat16* __restrict__ Alo,
    const __nv_bfloat16* __restrict__ Bhi, const __nv_bfloat16* __restrict__ Blo,
    const float* __restrict__ bias, float* __restrict__ Cf,
    __nv_bfloat16* __restrict__ Chi, __nv_bfloat16* __restrict__ Clo,
    size_t zA, size_t zB, size_t zC)
{
    extern __shared__ char smem[];
    const int tid = threadIdx.x, w = tid >> 5, lam = tid & 31;
    const int KA = (MODE == 0) ? KCONV : 512;
    const int NC = (MODE == 0) ? 19 : 8;
    const int m0 = (MODE == 0 ? blockIdx.x : blockIdx.y) * 128;   // A-side rows
    const int c0 = (MODE == 0 ? blockIdx.y : blockIdx.x) * 128;   // B-side cols
    const int z  = blockIdx.z;
    Ahi += (size_t)z * zA;  Alo += (size_t)z * zA;
    Bhi += (size_t)z * zB;  Blo += (size_t)z * zB;

    // ---- global->smem coords: 2 threads per row, halves of 64B each ----
    const int lrow = tid >> 1, lhalf = tid & 1;
    const size_t aBase = (size_t)(m0 + lrow) * KA + lhalf * 32;
    size_t bBase;
    if (MODE == 0) {
        const int col = c0 + lrow;
        bBase = (size_t)(col >> 5) * SLAB + (size_t)(col & 31) * 300 + lhalf * 32;
    } else {
        bBase = (size_t)(c0 + lrow) * 512 + lhalf * 32;
    }
    const u32 sb   = smem_u32(smem);
    const u32 dstA = sb + lrow * TROW + lhalf * 64;
    const u32 dstB = sb + 2 * TILE_B + lrow * TROW + lhalf * 64;

#define LOAD_STAGE(c, s) do {                                                        \
    const u32 so = (u32)(s) * STAGE;                                                 \
    const size_t ko = (size_t)(c) * 64;                                              \
    _Pragma("unroll") for (int q = 0; q < 4; ++q) {                                  \
        cp16(dstA + so + q*16,          Ahi + aBase + ko + q*8);                     \
        cp16(dstA + so + TILE_B + q*16, Alo + aBase + ko + q*8);                     \
    }                                                                                \
    if (MODE == 0) {                                                                 \
        _Pragma("unroll") for (int q = 0; q < 8; ++q) {                              \
            cp8(dstB + so + q*8,          Bhi + bBase + ko + q*4);                   \
            cp8(dstB + so + TILE_B + q*8, Blo + bBase + ko + q*4);                   \
        }                                                                            \
    } else {                                                                         \
        _Pragma("unroll") for (int q = 0; q < 4; ++q) {                              \
            cp16(dstB + so + q*16,          Bhi + bBase + ko + q*8);                 \
            cp16(dstB + so + TILE_B + q*16, Blo + bBase + ko + q*8);                 \
        }                                                                            \
    }                                                                                \
    CP_COMMIT();                                                                     \
} while (0)

    // ---- warp/lane fragment coords ----
    const int wm = (w >> 2) * 64, wn = (w & 3) * 32;
    const int aRow  = (lam & 7) + ((lam >> 3) & 1) * 8;
    const u32 aKoff = (lam >> 4) * 16;
    const int bRow  = (lam & 7) + (lam >> 4) * 8;
    const u32 bKoff = ((lam >> 3) & 1) * 16;

    float acc[4][4][4];
#pragma unroll
    for (int mi = 0; mi < 4; ++mi)
#pragma unroll
        for (int ni = 0; ni < 4; ++ni)
#pragma unroll
            for (int q = 0; q < 4; ++q) acc[mi][ni][q] = 0.f;

    LOAD_STAGE(0, 0);

    for (int c = 0; c < NC; ++c) {
        const int s = c & 1;
        if (c + 1 < NC) { LOAD_STAGE(c + 1, (c + 1) & 1); CP_WAIT(1); }
        else            { CP_WAIT(0); }
        __syncthreads();

        const u32 stA = sb + s * STAGE;
        const u32 stB = stA + 2 * TILE_B;
#pragma unroll
        for (int kk = 0; kk < 4; ++kk) {
            u32 ah[4][4], al[4][4], bh[4][2], bl[4][2];
#pragma unroll
            for (int mi = 0; mi < 4; ++mi) {
                const u32 a = stA + (wm + mi*16 + aRow) * TROW + kk*32 + aKoff;
                LDSM4(ah[mi], a);
                LDSM4(al[mi], a + TILE_B);
            }
#pragma unroll
            for (int nt = 0; nt < 2; ++nt) {
                const u32 a = stB + (wn + nt*16 + bRow) * TROW + kk*32 + bKoff;
                u32 t[4];
                LDSM4(t, a);
                bh[2*nt][0] = t[0]; bh[2*nt][1] = t[1];
                bh[2*nt+1][0] = t[2]; bh[2*nt+1][1] = t[3];
                LDSM4(t, a + TILE_B);
                bl[2*nt][0] = t[0]; bl[2*nt][1] = t[1];
                bl[2*nt+1][0] = t[2]; bl[2*nt+1][1] = t[3];
            }
#pragma unroll
            for (int mi = 0; mi < 4; ++mi)
#pragma unroll
                for (int ni = 0; ni < 4; ++ni) {
                    mma16816(acc[mi][ni], ah[mi], bh[ni]);
                    mma16816(acc[mi][ni], ah[mi], bl[ni]);
                    mma16816(acc[mi][ni], al[mi], bh[ni]);
                }
        }
        __syncthreads();
    }

    // ---- epilogue ----
    const int g = lam >> 2, i2 = (lam & 3) * 2;
    if (MODE == 0) {
        const int label = blockIdx.y * 4 + (w & 3);
#pragma unroll
        for (int mi = 0; mi < 4; ++mi) {
            float x0 = -FLT_MAX, x1 = -FLT_MAX;
#pragma unroll
            for (int ni = 0; ni < 4; ++ni)
#pragma unroll
                for (int j = 0; j < 2; ++j) {
                    const int t = ni * 8 + i2 + j;
                    if (t < 29) {
                        x0 = fmaxf(x0, acc[mi][ni][j]);
                        x1 = fmaxf(x1, acc[mi][ni][2 + j]);
                    }
                }
            x0 = fmaxf(x0, __shfl_xor_sync(0xffffffffu, x0, 1));
            x0 = fmaxf(x0, __shfl_xor_sync(0xffffffffu, x0, 2));
            x1 = fmaxf(x1, __shfl_xor_sync(0xffffffffu, x1, 1));
            x1 = fmaxf(x1, __shfl_xor_sync(0xffffffffu, x1, 2));
            if ((lam & 3) == 0) {
                const int f0 = m0 + wm + mi * 16 + g;
                float v = fmaxf(x0 + bias[f0], 0.f);
                __nv_bfloat16 h, l; split2(v, h, l);
                Chi[(size_t)label * FEAT + f0] = h;
                Clo[(size_t)label * FEAT + f0] = l;
                const int f1 = f0 + 8;
                v = fmaxf(x1 + bias[f1], 0.f);
                split2(v, h, l);
                Chi[(size_t)label * FEAT + f1] = h;
                Clo[(size_t)label * FEAT + f1] = l;
            }
        }
    } else if (MODE == 1) {
#pragma unroll
        for (int mi = 0; mi < 4; ++mi)
#pragma unroll
            for (int ni = 0; ni < 4; ++ni) {
                const int row = m0 + wm + mi * 16 + g;
                const int col = c0 + wn + ni * 8 + i2;
                __nv_bfloat16 h, l;
                float v = acc[mi][ni][0] + bias[col];
                split2(v, h, l); Chi[(size_t)row*512 + col] = h;     Clo[(size_t)row*512 + col] = l;
                v = acc[mi][ni][1] + bias[col + 1];
                split2(v, h, l); Chi[(size_t)row*512 + col + 1] = h; Clo[(size_t)row*512 + col + 1] = l;
                v = acc[mi][ni][2] + bias[col];
                split2(v, h, l); Chi[(size_t)(row+8)*512 + col] = h; Clo[(size_t)(row+8)*512 + col] = l;
                v = acc[mi][ni][3] + bias[col + 1];
                split2(v, h, l); Chi[(size_t)(row+8)*512 + col + 1] = h; Clo[(size_t)(row+8)*512 + col + 1] = l;
            }
    } else {
        float* base = Cf + (size_t)z * zC;
#pragma unroll
        for (int mi = 0; mi < 4; ++mi)
#pragma unroll
            for (int ni = 0; ni < 4; ++ni) {
                const int row = m0 + wm + mi * 16 + g;
                const int col = c0 + wn + ni * 8 + i2;
                *(float2*)(base + (size_t)row * 512 + col) =
                    make_float2(acc[mi][ni][0], acc[mi][ni][1]);
                *(float2*)(base + (size_t)(row + 8) * 512 + col) =
                    make_float2(acc[mi][ni][2], acc[mi][ni][3]);
            }
    }
#undef LOAD_STAGE
}

// ---------------- conversion kernels ----------------
__global__ void pad_lab() {
    int i = blockIdx.x * 256 + threadIdx.x;            // 2048
    g_lab_hi[NLAB*SLAB + i] = __float2bfloat16(0.f);
    g_lab_lo[NLAB*SLAB + i] = __float2bfloat16(0.f);
}
__global__ void cvt_lab(const float* __restrict__ in) {
    int i = blockIdx.x * 256 + threadIdx.x;            // 39321600 exact
    __nv_bfloat16 h, l; split2(in[i], h, l);
    g_lab_hi[i] = h; g_lab_lo[i] = l;
}
__global__ void cvt_wr(const float* __restrict__ cw) {
    int i = blockIdx.x * 256 + threadIdx.x;            // 512*1216 exact
    int f = i / KCONV, j = i % KCONV;
    float v = (j < 1200) ? cw[f * 1200 + (j % 300) * 4 + (j / 300)] : 0.f;
    __nv_bfloat16 h, l; split2(v, h, l);
    g_wr_hi[i] = h; g_wr_lo[i] = l;
}
__global__ void cvt_x(const float* __restrict__ x) {
    int i = blockIdx.x * 256 + threadIdx.x;            // 4194304 exact
    __nv_bfloat16 h, l; split2(x[i], h, l);
    g_x_hi[i] = h; g_x_lo[i] = l;
}
__global__ void cvt_xt(const float* __restrict__ x) {
    int i = blockIdx.x * 256 + threadIdx.x;            // 4194304 exact
    int l = i & 511, f = (i >> 9) & 511, b = i >> 18;
    __nv_bfloat16 h, lo; split2(x[(b << 18) + (l << 9) + f], h, lo);
    g_xt_hi[i] = h; g_xt_lo[i] = lo;
}
__global__ void cvt_lw(const float* __restrict__ lw) {
    int i = blockIdx.x * 256 + threadIdx.x;            // 262144 exact
    __nv_bfloat16 h, l; split2(lw[i], h, l);
    g_lw_hi[i] = h; g_lw_lo[i] = l;
}

// ---------------- softmax over L=512, outputs split bf16 ----------------
__global__ void softmax_kernel(const float* __restrict__ S,
                               __nv_bfloat16* __restrict__ Ph,
                               __nv_bfloat16* __restrict__ Pl) {
    const size_t row = blockIdx.x;
    const float* p = S + row * 512;
    const int tid = threadIdx.x;   // 128
    float v0 = p[tid], v1 = p[tid + 128], v2 = p[tid + 256], v3 = p[tid + 384];
    float mx = fmaxf(fmaxf(v0, v1), fmaxf(v2, v3));
#pragma unroll
    for (int o = 16; o > 0; o >>= 1) mx = fmaxf(mx, __shfl_xor_sync(0xffffffffu, mx, o));
    __shared__ float sm[4], ss[4];
    if ((tid & 31) == 0) sm[tid >> 5] = mx;
    __syncthreads();
    mx = fmaxf(fmaxf(sm[0], sm[1]), fmaxf(sm[2], sm[3]));
    v0 = expf(v0 - mx); v1 = expf(v1 - mx); v2 = expf(v2 - mx); v3 = expf(v3 - mx);
    float s = v0 + v1 + v2 + v3;
#pragma unroll
    for (int o = 16; o > 0; o >>= 1) s += __shfl_xor_sync(0xffffffffu, s, o);
    if ((tid & 31) == 0) ss[tid >> 5] = s;
    __syncthreads();
    s = ss[0] + ss[1] + ss[2] + ss[3];
    const float inv = 1.0f / s;
    const size_t b = row * 512;
    __nv_bfloat16 h, l;
    split2(v0 * inv, h, l); Ph[b + tid]       = h; Pl[b + tid]       = l;
    split2(v1 * inv, h, l); Ph[b + tid + 128] = h; Pl[b + tid + 128] = l;
    split2(v2 * inv, h, l); Ph[b + tid + 256] = h; Pl[b + tid + 256] = l;
    split2(v3 * inv, h, l); Ph[b + tid + 384] = h; Pl[b + tid + 384] = l;
}

// ---------------- launch ----------------
extern "C" void kernel_launch(void* const* d_in, const int* in_sizes, int n_in,
                              void* d_out, int out_size) {
    const float *x = nullptr, *lab = nullptr, *cw = nullptr,
                *cb = nullptr, *lw = nullptr, *lb = nullptr;
    for (int i = 0; i < n_in; ++i) {
        switch (in_sizes[i]) {
            case 4194304:  x   = (const float*)d_in[i]; break;
            case 39321600: lab = (const float*)d_in[i]; break;
            case 614400:   cw  = (const float*)d_in[i]; break;
            case 262144:   lw  = (const float*)d_in[i]; break;
            case 512:      if (!cb) cb = (const float*)d_in[i];
                           else     lb = (const float*)d_in[i];
                           break;
            default: break;   // label_length unused
        }
    }

    __nv_bfloat16 *labh, *labl, *wrh, *wrl, *xh, *xl, *xth, *xtl, *lwh, *lwl,
                  *lr0h, *lr0l, *lrh, *lrl, *Ph, *Pl;
    float *pS;
    cudaGetSymbolAddress((void**)&labh, g_lab_hi); cudaGetSymbolAddress((void**)&labl, g_lab_lo);
    cudaGetSymbolAddress((void**)&wrh,  g_wr_hi);  cudaGetSymbolAddress((void**)&wrl,  g_wr_lo);
    cudaGetSymbolAddress((void**)&xh,   g_x_hi);   cudaGetSymbolAddress((void**)&xl,   g_x_lo);
    cudaGetSymbolAddress((void**)&xth,  g_xt_hi);  cudaGetSymbolAddress((void**)&xtl,  g_xt_lo);
    cudaGetSymbolAddress((void**)&lwh,  g_lw_hi);  cudaGetSymbolAddress((void**)&lwl,  g_lw_lo);
    cudaGetSymbolAddress((void**)&lr0h, g_lr0_hi); cudaGetSymbolAddress((void**)&lr0l, g_lr0_lo);
    cudaGetSymbolAddress((void**)&lrh,  g_lr_hi);  cudaGetSymbolAddress((void**)&lrl,  g_lr_lo);
    cudaGetSymbolAddress((void**)&Ph,   g_P_hi);   cudaGetSymbolAddress((void**)&Pl,   g_P_lo);
    cudaGetSymbolAddress((void**)&pS,   g_S);

    cudaFuncSetAttribute(tgemm<0>, cudaFuncAttributeMaxDynamicSharedMemorySize, SMEM_TOTAL);
    cudaFuncSetAttribute(tgemm<1>, cudaFuncAttributeMaxDynamicSharedMemorySize, SMEM_TOTAL);
    cudaFuncSetAttribute(tgemm<2>, cudaFuncAttributeMaxDynamicSharedMemorySize, SMEM_TOTAL);
    cudaFuncSetAttribute(tgemm<3>, cudaFuncAttributeMaxDynamicSharedMemorySize, SMEM_TOTAL);

    pad_lab<<<8, 256>>>();
    cvt_lab<<<153600, 256>>>(lab);
    cvt_wr <<<2432,   256>>>(cw);
    cvt_x  <<<16384,  256>>>(x);
    cvt_xt <<<16384,  256>>>(x);
    cvt_lw <<<1024,   256>>>(lw);

    // conv: C[f, (n,t)], maxpool+bias+relu -> lr0 hi/lo
    tgemm<0><<<dim3(4, 1024, 1), 256, SMEM_TOTAL>>>(wrh, wrl, labh, labl, cb,
                                                    nullptr, lr0h, lr0l, 0, 0, 0);
    // linear: lr = lr0 @ lin_w^T + lin_b (both operands k(f_in)-major)
    tgemm<1><<<dim3(4, 32, 1),   256, SMEM_TOTAL>>>(lr0h, lr0l, lwh, lwl, lb,
                                                    nullptr, lrh, lrl, 0, 0, 0);
    // logits: S[b,n,l] = lr[n,:] . x[b,l,:]
    tgemm<2><<<dim3(4, 32, 16),  256, SMEM_TOTAL>>>(lrh, lrl, xh, xl, nullptr,
                                                    pS, nullptr, nullptr,
                                                    0, (size_t)LL * FEAT, (size_t)NLAB * LL);
    softmax_kernel<<<65536, 128>>>(pS, Ph, Pl);
    // out: O[b,n,f] = P[b,n,:] . xT[b,f,:]
    tgemm<3><<<dim3(4, 32, 16),  256, SMEM_TOTAL>>>(Ph, Pl, xth, xtl, nullptr,
                                                    (float*)d_out, nullptr, nullptr,
                                                    (size_t)NLAB * LL, (size_t)FEAT * LL,
                                                    (size_t)NLAB * FEAT);
}